// round 1
// baseline (speedup 1.0000x reference)
#include <cuda_runtime.h>

#define NN   16384
#define EE   524288
#define DIN  256
#define DOUT 128
#define X_ELEMS (NN * DOUT)
#define A_ELEMS ((size_t)NN * (size_t)NN)

// Scratch (no allocations allowed) — re-initialized every launch for graph replay determinism.
__device__ float g_s[EE];
__device__ float g_smax[NN];
__device__ float g_ssum[NN];
__device__ float g_sq[NN];

__global__ void init_kernel() {
    int i = blockIdx.x * blockDim.x + threadIdx.x;
    if (i < NN) { g_smax[i] = -3.0e38f; g_ssum[i] = 0.0f; }
}

// x = In[16384,256] @ W[256,128], fp32. 64-row tile per block, full 128 cols.
__global__ __launch_bounds__(256) void gemm_kernel(const float* __restrict__ In,
                                                   const float* __restrict__ W,
                                                   float* __restrict__ X) {
    __shared__ float As[64][32];
    __shared__ float Bs[32][128];
    const int tid  = threadIdx.x;
    const int brow = blockIdx.x * 64;
    const int tcol = (tid & 15) * 8;   // 8 output cols
    const int trow = (tid >> 4) * 4;   // 4 output rows

    float acc[4][8];
#pragma unroll
    for (int i = 0; i < 4; i++)
#pragma unroll
        for (int j = 0; j < 8; j++) acc[i][j] = 0.0f;

    for (int k0 = 0; k0 < DIN; k0 += 32) {
#pragma unroll
        for (int i = 0; i < 2; i++) {
            int idx = tid + i * 256;          // 512 float4 loads for 64x32 tile
            int r = idx >> 3;
            int c = (idx & 7) << 2;
            float4 v = *(const float4*)(In + (size_t)(brow + r) * DIN + k0 + c);
            *(float4*)&As[r][c] = v;
        }
#pragma unroll
        for (int i = 0; i < 4; i++) {
            int idx = tid + i * 256;          // 1024 float4 loads for 32x128 tile
            int r = idx >> 5;
            int c = (idx & 31) << 2;
            float4 v = *(const float4*)(W + (size_t)(k0 + r) * DOUT + c);
            *(float4*)&Bs[r][c] = v;
        }
        __syncthreads();
#pragma unroll
        for (int k = 0; k < 32; k++) {
            float4 b0 = *(float4*)&Bs[k][tcol];
            float4 b1 = *(float4*)&Bs[k][tcol + 4];
            float b[8] = {b0.x, b0.y, b0.z, b0.w, b1.x, b1.y, b1.z, b1.w};
#pragma unroll
            for (int i = 0; i < 4; i++) {
                float av = As[trow + i][k];
#pragma unroll
                for (int j = 0; j < 8; j++) acc[i][j] = fmaf(av, b[j], acc[i][j]);
            }
        }
        __syncthreads();
    }
#pragma unroll
    for (int i = 0; i < 4; i++) {
        float4 o0 = {acc[i][0], acc[i][1], acc[i][2], acc[i][3]};
        float4 o1 = {acc[i][4], acc[i][5], acc[i][6], acc[i][7]};
        size_t base = (size_t)(brow + trow + i) * DOUT + tcol;
        *(float4*)(X + base)     = o0;
        *(float4*)(X + base + 4) = o1;
    }
}

// Per-node squared L2 norm of x (one warp per node).
__global__ void sq_kernel(const float* __restrict__ X) {
    int w    = (blockIdx.x * blockDim.x + threadIdx.x) >> 5;
    int lane = threadIdx.x & 31;
    if (w >= NN) return;
    float4 v = *(const float4*)(X + (size_t)w * DOUT + lane * 4);
    float t = v.x * v.x + v.y * v.y + v.z * v.z + v.w * v.w;
#pragma unroll
    for (int o = 16; o; o >>= 1) t += __shfl_down_sync(0xffffffffu, t, o);
    if (lane == 0) g_sq[w] = t;
}

// Per-edge score: s = (sum_d relu(xi_d*xj_d)*a_d)/sqrt(sq_i*sq_j), gated to -9e15.
// One warp per edge; also atomic-max into per-row smax.
__global__ __launch_bounds__(256) void score_kernel(const float* __restrict__ X,
                                                    const int* __restrict__ edge,
                                                    const float* __restrict__ a) {
    int e    = (int)((blockIdx.x * (unsigned)blockDim.x + threadIdx.x) >> 5);
    int lane = threadIdx.x & 31;
    if (e >= EE) return;
    int row = edge[e];
    int col = edge[EE + e];

    float4 xi = *(const float4*)(X + (size_t)row * DOUT + lane * 4);
    float4 xj = *(const float4*)(X + (size_t)col * DOUT + lane * 4);
    float4 av = *(const float4*)(a + lane * 4);

    float t = fmaxf(xi.x * xj.x, 0.0f) * av.x
            + fmaxf(xi.y * xj.y, 0.0f) * av.y
            + fmaxf(xi.z * xj.z, 0.0f) * av.z
            + fmaxf(xi.w * xj.w, 0.0f) * av.w;
#pragma unroll
    for (int o = 16; o; o >>= 1) t += __shfl_down_sync(0xffffffffu, t, o);

    if (lane == 0) {
        float s;
        if (t > 0.0f) s = t * rsqrtf(g_sq[row] * g_sq[col]);
        else          s = -9e15f;
        g_s[e] = s;
        // float atomic max via CAS loop
        float* addr = &g_smax[row];
        int old = __float_as_int(*addr);
        while (s > __int_as_float(old)) {
            int prev = atomicCAS((int*)addr, old, __float_as_int(s));
            if (prev == old) break;
            old = prev;
        }
    }
}

// ex = exp(s - smax[row]); accumulate per-row sum.
__global__ void expsum_kernel(const int* __restrict__ edge) {
    int e = blockIdx.x * blockDim.x + threadIdx.x;
    if (e >= EE) return;
    int row = edge[e];
    float ex = __expf(g_s[e] - g_smax[row]);
    g_s[e] = ex;
    atomicAdd(&g_ssum[row], ex);
}

// vals = ex / ssum[row]; scatter-add into dense A (duplicate edges accumulate).
__global__ void scatter_kernel(const int* __restrict__ edge, float* __restrict__ A) {
    int e = blockIdx.x * blockDim.x + threadIdx.x;
    if (e >= EE) return;
    int row = edge[e];
    int col = edge[EE + e];
    float v = g_s[e] / g_ssum[row];
    atomicAdd(A + (size_t)row * NN + col, v);
}

extern "C" void kernel_launch(void* const* d_in, const int* in_sizes, int n_in,
                              void* d_out, int out_size) {
    const float* In   = (const float*)d_in[0];   // [16384, 256]
    const int*   edge = (const int*)d_in[1];     // [2, 524288]
    const float* W    = (const float*)d_in[2];   // [256, 128]
    const float* a    = (const float*)d_in[3];   // [128, 1]
    float* X = (float*)d_out;                    // [16384, 128]
    float* A = X + X_ELEMS;                      // [16384, 16384]

    cudaMemsetAsync(A, 0, A_ELEMS * sizeof(float), 0);
    init_kernel<<<(NN + 255) / 256, 256>>>();
    gemm_kernel<<<NN / 64, 256>>>(In, W, X);
    sq_kernel<<<NN / 8, 256>>>(X);
    score_kernel<<<EE / 8, 256>>>(X, edge, a);
    expsum_kernel<<<EE / 256, 256>>>(edge);
    scatter_kernel<<<EE / 256, 256>>>(edge, A);
}

// round 2
// speedup vs baseline: 1.3762x; 1.3762x over previous
#include <cuda_runtime.h>

#define NN   16384
#define EE   524288
#define DIN  256
#define DOUT 128
#define X_ELEMS (NN * DOUT)

// A = 16384*16384 floats = 1,073,741,824 bytes total.
// gemm zeroes first 256 * 512KB = 134,217,728 bytes.
// score zeroes remaining 939,524,096 bytes: 65536 blocks * 14336 bytes.
#define GEMM_Z_F4_PER_BLOCK   32768    // 512 KB / 16
#define SCORE_Z_F4_PER_BLOCK  896      // 14336 B / 16
#define SCORE_Z_OFF_F4        8388608  // 134217728 / 16

// Scratch (no allocations allowed). Re-zeroed inside gemm every launch.
__device__ float g_s[EE];      // per-edge exp(s)
__device__ float g_ssum[NN];   // per-row sum of exp(s)
__device__ int   g_cnt[NN];    // per-row edge count (degenerate-row fallback)
__device__ float g_sq[NN];     // per-row squared L2 norm of x

// x = In[16384,256] @ W[256,128]. Also: zeroes a 512KB chunk of A, zeroes
// ssum/cnt, and computes per-row squared norms from register accumulators.
__global__ __launch_bounds__(256) void gemm_kernel(const float* __restrict__ In,
                                                   const float* __restrict__ W,
                                                   float* __restrict__ X,
                                                   float* __restrict__ A) {
    // --- async zero of A chunk (streaming stores, bypass-ish L2) ---
    {
        float4 z4 = make_float4(0.f, 0.f, 0.f, 0.f);
        float4* zdst = reinterpret_cast<float4*>(A) + (size_t)blockIdx.x * GEMM_Z_F4_PER_BLOCK;
#pragma unroll 4
        for (int i = threadIdx.x; i < GEMM_Z_F4_PER_BLOCK; i += 256)
            __stcs(zdst + i, z4);
    }
    // --- zero softmax accumulators (rows b*64 .. b*64+63) ---
    if (threadIdx.x < 64) {
        int r = blockIdx.x * 64 + threadIdx.x;
        g_ssum[r] = 0.0f;
        g_cnt[r]  = 0;
    }

    __shared__ float As[64][32];
    __shared__ float Bs[32][128];
    __shared__ float ssq[64];
    const int tid  = threadIdx.x;
    const int brow = blockIdx.x * 64;
    const int tcol = (tid & 15) * 8;
    const int trow = (tid >> 4) * 4;
    if (tid < 64) ssq[tid] = 0.0f;

    float acc[4][8];
#pragma unroll
    for (int i = 0; i < 4; i++)
#pragma unroll
        for (int j = 0; j < 8; j++) acc[i][j] = 0.0f;

    for (int k0 = 0; k0 < DIN; k0 += 32) {
#pragma unroll
        for (int i = 0; i < 2; i++) {
            int idx = tid + i * 256;
            int r = idx >> 3;
            int c = (idx & 7) << 2;
            float4 v = *(const float4*)(In + (size_t)(brow + r) * DIN + k0 + c);
            *(float4*)&As[r][c] = v;
        }
#pragma unroll
        for (int i = 0; i < 4; i++) {
            int idx = tid + i * 256;
            int r = idx >> 5;
            int c = (idx & 31) << 2;
            float4 v = *(const float4*)(W + (size_t)(k0 + r) * DOUT + c);
            *(float4*)&Bs[r][c] = v;
        }
        __syncthreads();
#pragma unroll
        for (int k = 0; k < 32; k++) {
            float4 b0 = *(float4*)&Bs[k][tcol];
            float4 b1 = *(float4*)&Bs[k][tcol + 4];
            float b[8] = {b0.x, b0.y, b0.z, b0.w, b1.x, b1.y, b1.z, b1.w};
#pragma unroll
            for (int i = 0; i < 4; i++) {
                float av = As[trow + i][k];
#pragma unroll
                for (int j = 0; j < 8; j++) acc[i][j] = fmaf(av, b[j], acc[i][j]);
            }
        }
        __syncthreads();
    }
#pragma unroll
    for (int i = 0; i < 4; i++) {
        float4 o0 = {acc[i][0], acc[i][1], acc[i][2], acc[i][3]};
        float4 o1 = {acc[i][4], acc[i][5], acc[i][6], acc[i][7]};
        size_t base = (size_t)(brow + trow + i) * DOUT + tcol;
        *(float4*)(X + base)     = o0;
        *(float4*)(X + base + 4) = o1;
        // partial squared norm for this row from registers
        float p = acc[i][0]*acc[i][0] + acc[i][1]*acc[i][1] + acc[i][2]*acc[i][2] + acc[i][3]*acc[i][3]
                + acc[i][4]*acc[i][4] + acc[i][5]*acc[i][5] + acc[i][6]*acc[i][6] + acc[i][7]*acc[i][7];
        atomicAdd(&ssq[trow + i], p);
    }
    __syncthreads();
    if (tid < 64) g_sq[brow + tid] = ssq[tid];
}

// Per-edge: ex = exp(dot(relu(xi*xj),a) * rsqrt(sq_i*sq_j)) if dot>0 else 0.
// Accumulates per-row ssum and cnt. Also zeroes a 14KB chunk of A.
__global__ __launch_bounds__(256) void score_kernel(const float* __restrict__ X,
                                                    const int* __restrict__ edge,
                                                    const float* __restrict__ a,
                                                    float* __restrict__ A) {
    // --- async zero of A chunk ---
    {
        float4 z4 = make_float4(0.f, 0.f, 0.f, 0.f);
        float4* zdst = reinterpret_cast<float4*>(A) + SCORE_Z_OFF_F4
                     + (size_t)blockIdx.x * SCORE_Z_F4_PER_BLOCK;
#pragma unroll
        for (int i = threadIdx.x; i < SCORE_Z_F4_PER_BLOCK; i += 256)
            __stcs(zdst + i, z4);
    }

    int e    = (int)((blockIdx.x * 256u + threadIdx.x) >> 5);
    int lane = threadIdx.x & 31;
    if (e >= EE) return;
    int row = edge[e];
    int col = edge[EE + e];

    float4 xi = *(const float4*)(X + (size_t)row * DOUT + lane * 4);
    float4 xj = *(const float4*)(X + (size_t)col * DOUT + lane * 4);
    float4 av = *(const float4*)(a + lane * 4);

    float t = fmaxf(xi.x * xj.x, 0.0f) * av.x
            + fmaxf(xi.y * xj.y, 0.0f) * av.y
            + fmaxf(xi.z * xj.z, 0.0f) * av.z
            + fmaxf(xi.w * xj.w, 0.0f) * av.w;
#pragma unroll
    for (int o = 16; o; o >>= 1) t += __shfl_down_sync(0xffffffffu, t, o);

    if (lane == 0) {
        // s in (0, ~1.4] when gated-in => exp(s) cannot overflow; max-shift
        // is mathematically redundant here. Gated-out edges contribute 0
        // (matches exp(NEG_BIG - smax) when smax>0; all-gated rows handled
        // via g_cnt in scatter).
        float ex = 0.0f;
        if (t > 0.0f) ex = __expf(t * rsqrtf(g_sq[row] * g_sq[col]));
        g_s[e] = ex;
        atomicAdd(&g_ssum[row], ex);
        atomicAdd(&g_cnt[row], 1);
    }
}

// vals = ex / ssum[row] (or 1/cnt for all-gated rows); scatter-add into A.
__global__ void scatter_kernel(const int* __restrict__ edge, float* __restrict__ A) {
    int e = blockIdx.x * blockDim.x + threadIdx.x;
    if (e >= EE) return;
    int row = edge[e];
    int col = edge[EE + e];
    float denom = g_ssum[row];
    float v = (denom > 0.0f) ? (g_s[e] / denom) : (1.0f / (float)g_cnt[row]);
    atomicAdd(A + (size_t)row * NN + col, v);
}

extern "C" void kernel_launch(void* const* d_in, const int* in_sizes, int n_in,
                              void* d_out, int out_size) {
    const float* In   = (const float*)d_in[0];   // [16384, 256]
    const int*   edge = (const int*)d_in[1];     // [2, 524288]
    const float* W    = (const float*)d_in[2];   // [256, 128]
    const float* a    = (const float*)d_in[3];   // [128, 1]
    float* X = (float*)d_out;                    // [16384, 128]
    float* A = X + X_ELEMS;                      // [16384, 16384]

    gemm_kernel<<<NN / 64, 256>>>(In, W, X, A);
    score_kernel<<<EE / 8, 256>>>(X, edge, a, A);
    scatter_kernel<<<EE / 256, 256>>>(edge, A);
}